// round 3
// baseline (speedup 1.0000x reference)
#include <cuda_runtime.h>
#include <cuda_bf16.h>
#include <stdint.h>

// Problem constants
#define Bv 2
#define Nv 4
#define Dv 48
#define Hv 28
#define Wv 60
#define Cv 64
#define NXv 192
#define NYv 192
#define NZv 1
#define NYNX (NYv * NXv)

// Channel-contiguous staging accumulator: [B*NY*NX][64] floats (18.9 MB).
// BSS-zeroed at module load; the transpose kernel restores it to zero every
// launch, so it is always zero when the scatter of the next launch begins.
__device__ float4 g_staging4[(size_t)Bv * NYv * NXv * (Cv / 4)];

// ---------------------------------------------------------------------------
// Per-block setup (in smem): invert intrinsics element-wise by det (matches
// LU back-substitution bit-for-bit on this matrix structure — validated
// rel_err 2.5e-7 in R1/R2), combine = R @ inv(K), stash translation.
// ---------------------------------------------------------------------------
__device__ __forceinline__ void compute_combine(
    const float* __restrict__ intr, const float* __restrict__ pose,
    int i, float* cm, float* tr) {
    const float* K = intr + i * 9;
    float a00 = K[0], a01 = K[1], a02 = K[2];
    float a10 = K[3], a11 = K[4], a12 = K[5];
    float a20 = K[6], a21 = K[7], a22 = K[8];

    float det = __fadd_rn(
        __fsub_rn(__fmul_rn(a00, __fsub_rn(__fmul_rn(a11, a22), __fmul_rn(a12, a21))),
                  __fmul_rn(a01, __fsub_rn(__fmul_rn(a10, a22), __fmul_rn(a12, a20)))),
        __fmul_rn(a02, __fsub_rn(__fmul_rn(a10, a21), __fmul_rn(a11, a20))));

    float inv[9];
    inv[0] = __fdiv_rn(__fsub_rn(__fmul_rn(a11, a22), __fmul_rn(a12, a21)), det);
    inv[1] = __fdiv_rn(__fsub_rn(__fmul_rn(a02, a21), __fmul_rn(a01, a22)), det);
    inv[2] = __fdiv_rn(__fsub_rn(__fmul_rn(a01, a12), __fmul_rn(a02, a11)), det);
    inv[3] = __fdiv_rn(__fsub_rn(__fmul_rn(a12, a20), __fmul_rn(a10, a22)), det);
    inv[4] = __fdiv_rn(__fsub_rn(__fmul_rn(a00, a22), __fmul_rn(a02, a20)), det);
    inv[5] = __fdiv_rn(__fsub_rn(__fmul_rn(a02, a10), __fmul_rn(a00, a12)), det);
    inv[6] = __fdiv_rn(__fsub_rn(__fmul_rn(a10, a21), __fmul_rn(a11, a20)), det);
    inv[7] = __fdiv_rn(__fsub_rn(__fmul_rn(a01, a20), __fmul_rn(a00, a21)), det);
    inv[8] = __fdiv_rn(__fsub_rn(__fmul_rn(a00, a11), __fmul_rn(a01, a10)), det);

    const float* P = pose + i * 16;
    #pragma unroll
    for (int r = 0; r < 3; r++) {
        float r0 = P[r * 4 + 0], r1 = P[r * 4 + 1], r2 = P[r * 4 + 2];
        #pragma unroll
        for (int c = 0; c < 3; c++) {
            cm[r * 3 + c] = __fadd_rn(
                __fadd_rn(__fmul_rn(r0, inv[0 * 3 + c]),
                          __fmul_rn(r1, inv[1 * 3 + c])),
                __fmul_rn(r2, inv[2 * 3 + c]));
        }
    }
    tr[0] = P[3];
    tr[1] = P[7];
    tr[2] = P[11];
}

__device__ __forceinline__ void red_v4(float* p, float4 a) {
    asm volatile("red.global.add.v4.f32 [%0], {%1, %2, %3, %4};" ::
                 "l"(p), "f"(a.x), "f"(a.y), "f"(a.z), "f"(a.w)
                 : "memory");
}

// ---------------------------------------------------------------------------
// Scatter: one warp = FOUR rays (8 lanes each, 8 channels per lane).
// Per ray: compute all 4 cell ids, then (fast path: all equal, which holds
// whenever the cameras share pose/intrinsics) issue all 8 float4 loads
// back-to-back (MLP 8) and flush once with two red.global.add.v4.f32.
// Generic fallback handles per-n differing cells.
// ---------------------------------------------------------------------------
__global__ __launch_bounds__(256) void fp_scatter_kernel(
    const float* __restrict__ x,
    const float* __restrict__ intr,
    const float* __restrict__ pose) {
    __shared__ float s_cm[Bv * Nv][9];
    __shared__ float s_tr[Bv * Nv][3];
    int t = threadIdx.x;
    if (t < Bv * Nv) compute_combine(intr, pose, t, s_cm[t], s_tr[t]);
    __syncthreads();

    const int P = Bv * Dv * Hv * Wv;  // 161280 rays
    int gwarp = (blockIdx.x * 256 + t) >> 5;
    int lane = t & 31;
    int r = gwarp * 4 + (lane >> 3);
    if (r >= P) return;
    int c8 = (lane & 7) * 8;  // channel group base

    int w = r % Wv;
    int tt = r / Wv;
    int h = tt % Hv;
    tt /= Hv;
    int d = tt % Dv;
    int b = tt / Dv;

    // Frustum point (linspace with forced endpoints, matching numpy/jnp)
    float du = __fdiv_rn((float)(Wv * 8 - 1), (float)(Wv - 1));  // 479/59
    float dv = __fdiv_rn((float)(Hv * 8 - 1), (float)(Hv - 1));  // 223/27
    float u = (w == Wv - 1) ? (float)(Wv * 8 - 1) : __fmul_rn((float)w, du);
    float v = (h == Hv - 1) ? (float)(Hv * 8 - 1) : __fmul_rn((float)h, dv);
    float dd = __fadd_rn(2.0f, (float)d);
    float ud = __fmul_rn(u, dd);
    float vd = __fmul_rn(v, dd);

    int cells[Nv];
    #pragma unroll
    for (int n = 0; n < Nv; n++) {
        const float* cm = s_cm[b * Nv + n];
        const float* tr = s_tr[b * Nv + n];
        float g0 = __fadd_rn(
            __fadd_rn(__fadd_rn(__fmul_rn(cm[0], ud), __fmul_rn(cm[1], vd)),
                      __fmul_rn(cm[2], dd)),
            tr[0]);
        float g1 = __fadd_rn(
            __fadd_rn(__fadd_rn(__fmul_rn(cm[3], ud), __fmul_rn(cm[4], vd)),
                      __fmul_rn(cm[5], dd)),
            tr[1]);
        float g2 = __fadd_rn(
            __fadd_rn(__fadd_rn(__fmul_rn(cm[6], ud), __fmul_rn(cm[7], vd)),
                      __fmul_rn(cm[8], dd)),
            tr[2]);
        int gx = (int)__fadd_rn(__fmul_rn(g0, 4.0f), 96.0f);
        int gy = (int)__fadd_rn(__fmul_rn(g1, 4.0f), 96.0f);
        int gz = (int)__fdiv_rn(__fadd_rn(g2, 10.0f), 20.0f);
        bool kept = (gx >= 0) & (gx < NXv) & (gy >= 0) & (gy < NYv) &
                    (gz >= 0) & (gz < NZv);
        cells[n] = kept ? ((b * NYv + gy) * NXv + gx) : -1;
    }

    // base x offset for (b, n=0, d, h, w), channel group c8
    size_t xoff = (size_t)(((b * Nv * Dv + d) * Hv + h) * Wv + w) * Cv + c8;
    const size_t nstride = (size_t)Dv * Hv * Wv * Cv;

    bool alleq = (cells[0] == cells[1]) & (cells[1] == cells[2]) &
                 (cells[2] == cells[3]);
    if (alleq) {
        int cell = cells[0];
        if (cell < 0) return;
        // Batch all 8 loads (MLP 8), then reduce, then one flush.
        float4 v0[Nv], v1[Nv];
        #pragma unroll
        for (int n = 0; n < Nv; n++) {
            const float4* p = (const float4*)(x + xoff + n * nstride);
            v0[n] = __ldg(p);
            v1[n] = __ldg(p + 1);
        }
        float4 a0 = v0[0], a1 = v1[0];
        #pragma unroll
        for (int n = 1; n < Nv; n++) {
            a0.x += v0[n].x; a0.y += v0[n].y; a0.z += v0[n].z; a0.w += v0[n].w;
            a1.x += v1[n].x; a1.y += v1[n].y; a1.z += v1[n].z; a1.w += v1[n].w;
        }
        float* p = (float*)g_staging4 + (size_t)cell * Cv + c8;
        red_v4(p, a0);
        red_v4(p + 4, a1);
    } else {
        // Generic path: flush on cell change (order matches n ascending)
        float4 a0 = make_float4(0, 0, 0, 0), a1 = make_float4(0, 0, 0, 0);
        int cur = -1;
        #pragma unroll
        for (int n = 0; n < Nv; n++) {
            if (cells[n] != cur) {
                if (cur >= 0) {
                    float* p = (float*)g_staging4 + (size_t)cur * Cv + c8;
                    red_v4(p, a0);
                    red_v4(p + 4, a1);
                }
                a0 = make_float4(0, 0, 0, 0);
                a1 = make_float4(0, 0, 0, 0);
                cur = cells[n];
            }
            if (cells[n] >= 0) {
                const float4* p = (const float4*)(x + xoff + n * nstride);
                float4 w0 = __ldg(p), w1 = __ldg(p + 1);
                a0.x += w0.x; a0.y += w0.y; a0.z += w0.z; a0.w += w0.w;
                a1.x += w1.x; a1.y += w1.y; a1.z += w1.z; a1.w += w1.w;
            }
        }
        if (cur >= 0) {
            float* p = (float*)g_staging4 + (size_t)cur * Cv + c8;
            red_v4(p, a0);
            red_v4(p + 4, a1);
        }
    }
}

// ---------------------------------------------------------------------------
// Transpose staging (B, NY, NX, C) -> out (B, C, NY, NX), float4 both ways,
// and restore staging to zero for the next launch (each thread zeroes the
// exact float4 it just read — no cross-thread hazard).
// Smem stride 65: bank = (gx + c) % 32, conflict-free on both phases.
// ---------------------------------------------------------------------------
__global__ __launch_bounds__(256) void fp_transpose_kernel(float* __restrict__ out) {
    __shared__ float tile[32 * 65];
    int blk = blockIdx.x;
    int gxt = blk % (NXv / 32);
    int t1 = blk / (NXv / 32);
    int gy = t1 % NYv;
    int b = t1 / NYv;
    int gx0 = gxt * 32;
    int t = threadIdx.x;

    float4* src = g_staging4 + ((size_t)(b * NYv + gy) * NXv + gx0) * (Cv / 4);
    const float4 z4 = make_float4(0.f, 0.f, 0.f, 0.f);

    #pragma unroll
    for (int it = 0; it < 2; it++) {
        int uu = t + it * 256;       // 0..511 float4 units
        int gx = uu >> 4;
        int c4 = (uu & 15) * 4;
        float4 vv = src[uu];
        src[uu] = z4;                // restore zero for next launch
        tile[gx * 65 + c4 + 0] = vv.x;
        tile[gx * 65 + c4 + 1] = vv.y;
        tile[gx * 65 + c4 + 2] = vv.z;
        tile[gx * 65 + c4 + 3] = vv.w;
    }
    __syncthreads();

    #pragma unroll
    for (int it = 0; it < 2; it++) {
        int uu = t + it * 256;       // 0..511 output float4 units
        int gx4 = uu & 7;            // 4-wide gx group
        int c = uu >> 3;             // 0..63
        float4 o;
        o.x = tile[(gx4 * 4 + 0) * 65 + c];
        o.y = tile[(gx4 * 4 + 1) * 65 + c];
        o.z = tile[(gx4 * 4 + 2) * 65 + c];
        o.w = tile[(gx4 * 4 + 3) * 65 + c];
        float4* dst = (float4*)(out + (size_t)(b * Cv + c) * NYNX +
                                gy * NXv + gx0 + gx4 * 4);
        *dst = o;
    }
}

extern "C" void kernel_launch(void* const* d_in, const int* in_sizes, int n_in,
                              void* d_out, int out_size) {
    const float* x = (const float*)d_in[0];
    const float* intr = (const float*)d_in[1];
    const float* pose = (const float*)d_in[2];
    float* out = (float*)d_out;

    // 1) scatter (4 rays per warp, vector atomics into zeroed staging)
    const int P = Bv * Dv * Hv * Wv;      // 161280 rays
    int blocks = P / 4 / 8;               // 5040 blocks of 8 warps
    fp_scatter_kernel<<<blocks, 256>>>(x, intr, pose);

    // 2) transpose staging -> out (writes every element; re-zeroes staging)
    int tblocks = Bv * NYv * (NXv / 32);  // 2304
    fp_transpose_kernel<<<tblocks, 256>>>(out);
}

// round 4
// speedup vs baseline: 1.7021x; 1.7021x over previous
#include <cuda_runtime.h>
#include <cuda_bf16.h>
#include <stdint.h>

// Problem constants
#define Bv 2
#define Nv 4
#define Dv 48
#define Hv 28
#define Wv 60
#define Cv 64
#define NXv 192
#define NYv 192
#define NZv 1
#define NYNX (NYv * NXv)

// Channel-contiguous staging accumulator: [B*NY*NX][64] floats (18.9 MB).
// BSS-zeroed at module load; the transpose kernel restores it to zero at its
// tail every launch, so it is always zero when the next scatter begins.
__device__ float4 g_staging4[(size_t)Bv * NYv * NXv * (Cv / 4)];

// ---------------------------------------------------------------------------
// Per-block setup (in smem): invert intrinsics element-wise by det (matches
// LU back-substitution bit-for-bit on this matrix structure — validated
// rel_err 2.5e-7 across R1-R3), combine = R @ inv(K), stash translation.
// ---------------------------------------------------------------------------
__device__ __forceinline__ void compute_combine(
    const float* __restrict__ intr, const float* __restrict__ pose,
    int i, float* cm, float* tr) {
    const float* K = intr + i * 9;
    float a00 = K[0], a01 = K[1], a02 = K[2];
    float a10 = K[3], a11 = K[4], a12 = K[5];
    float a20 = K[6], a21 = K[7], a22 = K[8];

    float det = __fadd_rn(
        __fsub_rn(__fmul_rn(a00, __fsub_rn(__fmul_rn(a11, a22), __fmul_rn(a12, a21))),
                  __fmul_rn(a01, __fsub_rn(__fmul_rn(a10, a22), __fmul_rn(a12, a20)))),
        __fmul_rn(a02, __fsub_rn(__fmul_rn(a10, a21), __fmul_rn(a11, a20))));

    float inv[9];
    inv[0] = __fdiv_rn(__fsub_rn(__fmul_rn(a11, a22), __fmul_rn(a12, a21)), det);
    inv[1] = __fdiv_rn(__fsub_rn(__fmul_rn(a02, a21), __fmul_rn(a01, a22)), det);
    inv[2] = __fdiv_rn(__fsub_rn(__fmul_rn(a01, a12), __fmul_rn(a02, a11)), det);
    inv[3] = __fdiv_rn(__fsub_rn(__fmul_rn(a12, a20), __fmul_rn(a10, a22)), det);
    inv[4] = __fdiv_rn(__fsub_rn(__fmul_rn(a00, a22), __fmul_rn(a02, a20)), det);
    inv[5] = __fdiv_rn(__fsub_rn(__fmul_rn(a02, a10), __fmul_rn(a00, a12)), det);
    inv[6] = __fdiv_rn(__fsub_rn(__fmul_rn(a10, a21), __fmul_rn(a11, a20)), det);
    inv[7] = __fdiv_rn(__fsub_rn(__fmul_rn(a01, a20), __fmul_rn(a00, a21)), det);
    inv[8] = __fdiv_rn(__fsub_rn(__fmul_rn(a00, a11), __fmul_rn(a01, a10)), det);

    const float* P = pose + i * 16;
    #pragma unroll
    for (int r = 0; r < 3; r++) {
        float r0 = P[r * 4 + 0], r1 = P[r * 4 + 1], r2 = P[r * 4 + 2];
        #pragma unroll
        for (int c = 0; c < 3; c++) {
            cm[r * 3 + c] = __fadd_rn(
                __fadd_rn(__fmul_rn(r0, inv[0 * 3 + c]),
                          __fmul_rn(r1, inv[1 * 3 + c])),
                __fmul_rn(r2, inv[2 * 3 + c]));
        }
    }
    tr[0] = P[3];
    tr[1] = P[7];
    tr[2] = P[11];
}

__device__ __forceinline__ void red_v4(float* p, float4 a) {
    asm volatile("red.global.add.v4.f32 [%0], {%1, %2, %3, %4};" ::
                 "l"(p), "f"(a.x), "f"(a.y), "f"(a.z), "f"(a.w)
                 : "memory");
}

// ---------------------------------------------------------------------------
// Scatter: one warp = FOUR rays (8 lanes each, 8 channels per lane).
// Per ray: compute all 4 cell ids, then (fast path: all equal, which holds
// whenever the cameras share pose/intrinsics) issue all 8 float4 loads
// back-to-back (MLP 8) and flush once with two red.global.add.v4.f32.
// Generic fallback handles per-n differing cells.  [unchanged from R3 —
// measured ~18.5 us]
// ---------------------------------------------------------------------------
__global__ __launch_bounds__(256) void fp_scatter_kernel(
    const float* __restrict__ x,
    const float* __restrict__ intr,
    const float* __restrict__ pose) {
    __shared__ float s_cm[Bv * Nv][9];
    __shared__ float s_tr[Bv * Nv][3];
    int t = threadIdx.x;
    if (t < Bv * Nv) compute_combine(intr, pose, t, s_cm[t], s_tr[t]);
    __syncthreads();

    const int P = Bv * Dv * Hv * Wv;  // 161280 rays
    int gwarp = (blockIdx.x * 256 + t) >> 5;
    int lane = t & 31;
    int r = gwarp * 4 + (lane >> 3);
    if (r >= P) return;
    int c8 = (lane & 7) * 8;  // channel group base

    int w = r % Wv;
    int tt = r / Wv;
    int h = tt % Hv;
    tt /= Hv;
    int d = tt % Dv;
    int b = tt / Dv;

    // Frustum point (linspace with forced endpoints, matching numpy/jnp)
    float du = __fdiv_rn((float)(Wv * 8 - 1), (float)(Wv - 1));  // 479/59
    float dv = __fdiv_rn((float)(Hv * 8 - 1), (float)(Hv - 1));  // 223/27
    float u = (w == Wv - 1) ? (float)(Wv * 8 - 1) : __fmul_rn((float)w, du);
    float v = (h == Hv - 1) ? (float)(Hv * 8 - 1) : __fmul_rn((float)h, dv);
    float dd = __fadd_rn(2.0f, (float)d);
    float ud = __fmul_rn(u, dd);
    float vd = __fmul_rn(v, dd);

    int cells[Nv];
    #pragma unroll
    for (int n = 0; n < Nv; n++) {
        const float* cm = s_cm[b * Nv + n];
        const float* tr = s_tr[b * Nv + n];
        float g0 = __fadd_rn(
            __fadd_rn(__fadd_rn(__fmul_rn(cm[0], ud), __fmul_rn(cm[1], vd)),
                      __fmul_rn(cm[2], dd)),
            tr[0]);
        float g1 = __fadd_rn(
            __fadd_rn(__fadd_rn(__fmul_rn(cm[3], ud), __fmul_rn(cm[4], vd)),
                      __fmul_rn(cm[5], dd)),
            tr[1]);
        float g2 = __fadd_rn(
            __fadd_rn(__fadd_rn(__fmul_rn(cm[6], ud), __fmul_rn(cm[7], vd)),
                      __fmul_rn(cm[8], dd)),
            tr[2]);
        int gx = (int)__fadd_rn(__fmul_rn(g0, 4.0f), 96.0f);
        int gy = (int)__fadd_rn(__fmul_rn(g1, 4.0f), 96.0f);
        int gz = (int)__fdiv_rn(__fadd_rn(g2, 10.0f), 20.0f);
        bool kept = (gx >= 0) & (gx < NXv) & (gy >= 0) & (gy < NYv) &
                    (gz >= 0) & (gz < NZv);
        cells[n] = kept ? ((b * NYv + gy) * NXv + gx) : -1;
    }

    size_t xoff = (size_t)(((b * Nv * Dv + d) * Hv + h) * Wv + w) * Cv + c8;
    const size_t nstride = (size_t)Dv * Hv * Wv * Cv;

    bool alleq = (cells[0] == cells[1]) & (cells[1] == cells[2]) &
                 (cells[2] == cells[3]);
    if (alleq) {
        int cell = cells[0];
        if (cell < 0) return;
        float4 v0[Nv], v1[Nv];
        #pragma unroll
        for (int n = 0; n < Nv; n++) {
            const float4* p = (const float4*)(x + xoff + n * nstride);
            v0[n] = __ldg(p);
            v1[n] = __ldg(p + 1);
        }
        float4 a0 = v0[0], a1 = v1[0];
        #pragma unroll
        for (int n = 1; n < Nv; n++) {
            a0.x += v0[n].x; a0.y += v0[n].y; a0.z += v0[n].z; a0.w += v0[n].w;
            a1.x += v1[n].x; a1.y += v1[n].y; a1.z += v1[n].z; a1.w += v1[n].w;
        }
        float* p = (float*)g_staging4 + (size_t)cell * Cv + c8;
        red_v4(p, a0);
        red_v4(p + 4, a1);
    } else {
        float4 a0 = make_float4(0, 0, 0, 0), a1 = make_float4(0, 0, 0, 0);
        int cur = -1;
        #pragma unroll
        for (int n = 0; n < Nv; n++) {
            if (cells[n] != cur) {
                if (cur >= 0) {
                    float* p = (float*)g_staging4 + (size_t)cur * Cv + c8;
                    red_v4(p, a0);
                    red_v4(p + 4, a1);
                }
                a0 = make_float4(0, 0, 0, 0);
                a1 = make_float4(0, 0, 0, 0);
                cur = cells[n];
            }
            if (cells[n] >= 0) {
                const float4* p = (const float4*)(x + xoff + n * nstride);
                float4 w0 = __ldg(p), w1 = __ldg(p + 1);
                a0.x += w0.x; a0.y += w0.y; a0.z += w0.z; a0.w += w0.w;
                a1.x += w1.x; a1.y += w1.y; a1.z += w1.z; a1.w += w1.w;
            }
        }
        if (cur >= 0) {
            float* p = (float*)g_staging4 + (size_t)cur * Cv + c8;
            red_v4(p, a0);
            red_v4(p + 4, a1);
        }
    }
}

// ---------------------------------------------------------------------------
// Transpose staging (B, NY, NX, C) -> out (B, C, NY, NX), float4 both ways.
// The staging re-zero is deferred to the KERNEL TAIL (after syncthreads and
// the output stores): the R3 regression came from issuing STG-zero 1 cycle
// after the LDG of the same address — the L1tex same-address WAR ordering
// parked each store behind its ~600-cycle load and backpressured the LSU.
// At the tail the loads completed long ago, so the zero stores are pure
// fire-and-forget. Only this block touches this staging region, so the
// post-barrier ordering is safe.
// ---------------------------------------------------------------------------
__global__ __launch_bounds__(256) void fp_transpose_kernel(float* __restrict__ out) {
    __shared__ float tile[32 * 65];
    int blk = blockIdx.x;
    int gxt = blk % (NXv / 32);
    int t1 = blk / (NXv / 32);
    int gy = t1 % NYv;
    int b = t1 / NYv;
    int gx0 = gxt * 32;
    int t = threadIdx.x;

    float4* src = g_staging4 + ((size_t)(b * NYv + gy) * NXv + gx0) * (Cv / 4);

    #pragma unroll
    for (int it = 0; it < 2; it++) {
        int uu = t + it * 256;       // 0..511 float4 units
        int gx = uu >> 4;
        int c4 = (uu & 15) * 4;
        float4 vv = src[uu];
        tile[gx * 65 + c4 + 0] = vv.x;
        tile[gx * 65 + c4 + 1] = vv.y;
        tile[gx * 65 + c4 + 2] = vv.z;
        tile[gx * 65 + c4 + 3] = vv.w;
    }
    __syncthreads();

    #pragma unroll
    for (int it = 0; it < 2; it++) {
        int uu = t + it * 256;       // 0..511 output float4 units
        int gx4 = uu & 7;            // 4-wide gx group
        int c = uu >> 3;             // 0..63
        float4 o;
        o.x = tile[(gx4 * 4 + 0) * 65 + c];
        o.y = tile[(gx4 * 4 + 1) * 65 + c];
        o.z = tile[(gx4 * 4 + 2) * 65 + c];
        o.w = tile[(gx4 * 4 + 3) * 65 + c];
        float4* dst = (float4*)(out + (size_t)(b * Cv + c) * NYNX +
                                gy * NXv + gx0 + gx4 * 4);
        *dst = o;
    }

    // Tail: restore staging to zero for the next graph replay.
    const float4 z4 = make_float4(0.f, 0.f, 0.f, 0.f);
    src[t] = z4;
    src[t + 256] = z4;
}

extern "C" void kernel_launch(void* const* d_in, const int* in_sizes, int n_in,
                              void* d_out, int out_size) {
    const float* x = (const float*)d_in[0];
    const float* intr = (const float*)d_in[1];
    const float* pose = (const float*)d_in[2];
    float* out = (float*)d_out;

    // 1) scatter (4 rays per warp, vector atomics into zeroed staging)
    const int P = Bv * Dv * Hv * Wv;      // 161280 rays
    int blocks = P / 4 / 8;               // 5040 blocks of 8 warps
    fp_scatter_kernel<<<blocks, 256>>>(x, intr, pose);

    // 2) transpose staging -> out; re-zeroes staging at its tail
    int tblocks = Bv * NYv * (NXv / 32);  // 2304
    fp_transpose_kernel<<<tblocks, 256>>>(out);
}

// round 6
// speedup vs baseline: 1.7039x; 1.0010x over previous
#include <cuda_runtime.h>
#include <cuda_bf16.h>
#include <stdint.h>

// Problem constants
#define Bv 2
#define Nv 4
#define Dv 48
#define Hv 28
#define Wv 60
#define Cv 64
#define NXv 192
#define NYv 192
#define NZv 1
#define NYNX (NYv * NXv)

// Channel-contiguous staging accumulator: [B*NY*NX][64] floats (18.9 MB).
// BSS-zeroed at module load; the transpose kernel restores it to zero at its
// tail every launch, so it is always zero when the next scatter begins.
__device__ float4 g_staging4[(size_t)Bv * NYv * NXv * (Cv / 4)];

// ---------------------------------------------------------------------------
// Per-block setup (in smem): invert intrinsics element-wise by det (matches
// LU back-substitution bit-for-bit on this matrix structure — validated
// rel_err 2.5e-7 across R1-R4), combine = R @ inv(K), stash translation.
// ---------------------------------------------------------------------------
__device__ __forceinline__ void compute_combine(
    const float* __restrict__ intr, const float* __restrict__ pose,
    int i, float* cm, float* tr) {
    const float* K = intr + i * 9;
    float a00 = K[0], a01 = K[1], a02 = K[2];
    float a10 = K[3], a11 = K[4], a12 = K[5];
    float a20 = K[6], a21 = K[7], a22 = K[8];

    float det = __fadd_rn(
        __fsub_rn(__fmul_rn(a00, __fsub_rn(__fmul_rn(a11, a22), __fmul_rn(a12, a21))),
                  __fmul_rn(a01, __fsub_rn(__fmul_rn(a10, a22), __fmul_rn(a12, a20)))),
        __fmul_rn(a02, __fsub_rn(__fmul_rn(a10, a21), __fmul_rn(a11, a20))));

    float inv[9];
    inv[0] = __fdiv_rn(__fsub_rn(__fmul_rn(a11, a22), __fmul_rn(a12, a21)), det);
    inv[1] = __fdiv_rn(__fsub_rn(__fmul_rn(a02, a21), __fmul_rn(a01, a22)), det);
    inv[2] = __fdiv_rn(__fsub_rn(__fmul_rn(a01, a12), __fmul_rn(a02, a11)), det);
    inv[3] = __fdiv_rn(__fsub_rn(__fmul_rn(a12, a20), __fmul_rn(a10, a22)), det);
    inv[4] = __fdiv_rn(__fsub_rn(__fmul_rn(a00, a22), __fmul_rn(a02, a20)), det);
    inv[5] = __fdiv_rn(__fsub_rn(__fmul_rn(a02, a10), __fmul_rn(a00, a12)), det);
    inv[6] = __fdiv_rn(__fsub_rn(__fmul_rn(a10, a21), __fmul_rn(a11, a20)), det);
    inv[7] = __fdiv_rn(__fsub_rn(__fmul_rn(a01, a20), __fmul_rn(a00, a21)), det);
    inv[8] = __fdiv_rn(__fsub_rn(__fmul_rn(a00, a11), __fmul_rn(a01, a10)), det);

    const float* P = pose + i * 16;
    #pragma unroll
    for (int r = 0; r < 3; r++) {
        float r0 = P[r * 4 + 0], r1 = P[r * 4 + 1], r2 = P[r * 4 + 2];
        #pragma unroll
        for (int c = 0; c < 3; c++) {
            cm[r * 3 + c] = __fadd_rn(
                __fadd_rn(__fmul_rn(r0, inv[0 * 3 + c]),
                          __fmul_rn(r1, inv[1 * 3 + c])),
                __fmul_rn(r2, inv[2 * 3 + c]));
        }
    }
    tr[0] = P[3];
    tr[1] = P[7];
    tr[2] = P[11];
}

__device__ __forceinline__ void red_v4(float* p, float4 a) {
    asm volatile("red.global.add.v4.f32 [%0], {%1, %2, %3, %4};" ::
                 "l"(p), "f"(a.x), "f"(a.y), "f"(a.z), "f"(a.w)
                 : "memory");
}

// ---------------------------------------------------------------------------
// Scatter: one warp = FOUR rays (8 lanes each, 8 channels per lane).
// Per ray: compute all 4 cell ids, then (fast path: all equal) issue all 8
// float4 loads back-to-back (MLP 8) and flush once with two
// red.global.add.v4.f32. Generic fallback handles per-n differing cells.
// [UNCHANGED from R3/R4 — measured at its DRAM read roofline ~20 us]
// ---------------------------------------------------------------------------
__global__ __launch_bounds__(256) void fp_scatter_kernel(
    const float* __restrict__ x,
    const float* __restrict__ intr,
    const float* __restrict__ pose) {
    __shared__ float s_cm[Bv * Nv][9];
    __shared__ float s_tr[Bv * Nv][3];
    int t = threadIdx.x;
    if (t < Bv * Nv) compute_combine(intr, pose, t, s_cm[t], s_tr[t]);
    __syncthreads();

    const int P = Bv * Dv * Hv * Wv;  // 161280 rays
    int gwarp = (blockIdx.x * 256 + t) >> 5;
    int lane = t & 31;
    int r = gwarp * 4 + (lane >> 3);
    if (r >= P) return;
    int c8 = (lane & 7) * 8;  // channel group base

    int w = r % Wv;
    int tt = r / Wv;
    int h = tt % Hv;
    tt /= Hv;
    int d = tt % Dv;
    int b = tt / Dv;

    // Frustum point (linspace with forced endpoints, matching numpy/jnp)
    float du = __fdiv_rn((float)(Wv * 8 - 1), (float)(Wv - 1));  // 479/59
    float dv = __fdiv_rn((float)(Hv * 8 - 1), (float)(Hv - 1));  // 223/27
    float u = (w == Wv - 1) ? (float)(Wv * 8 - 1) : __fmul_rn((float)w, du);
    float v = (h == Hv - 1) ? (float)(Hv * 8 - 1) : __fmul_rn((float)h, dv);
    float dd = __fadd_rn(2.0f, (float)d);
    float ud = __fmul_rn(u, dd);
    float vd = __fmul_rn(v, dd);

    int cells[Nv];
    #pragma unroll
    for (int n = 0; n < Nv; n++) {
        const float* cm = s_cm[b * Nv + n];
        const float* tr = s_tr[b * Nv + n];
        float g0 = __fadd_rn(
            __fadd_rn(__fadd_rn(__fmul_rn(cm[0], ud), __fmul_rn(cm[1], vd)),
                      __fmul_rn(cm[2], dd)),
            tr[0]);
        float g1 = __fadd_rn(
            __fadd_rn(__fadd_rn(__fmul_rn(cm[3], ud), __fmul_rn(cm[4], vd)),
                      __fmul_rn(cm[5], dd)),
            tr[1]);
        float g2 = __fadd_rn(
            __fadd_rn(__fadd_rn(__fmul_rn(cm[6], ud), __fmul_rn(cm[7], vd)),
                      __fmul_rn(cm[8], dd)),
            tr[2]);
        int gx = (int)__fadd_rn(__fmul_rn(g0, 4.0f), 96.0f);
        int gy = (int)__fadd_rn(__fmul_rn(g1, 4.0f), 96.0f);
        int gz = (int)__fdiv_rn(__fadd_rn(g2, 10.0f), 20.0f);
        bool kept = (gx >= 0) & (gx < NXv) & (gy >= 0) & (gy < NYv) &
                    (gz >= 0) & (gz < NZv);
        cells[n] = kept ? ((b * NYv + gy) * NXv + gx) : -1;
    }

    size_t xoff = (size_t)(((b * Nv * Dv + d) * Hv + h) * Wv + w) * Cv + c8;
    const size_t nstride = (size_t)Dv * Hv * Wv * Cv;

    bool alleq = (cells[0] == cells[1]) & (cells[1] == cells[2]) &
                 (cells[2] == cells[3]);
    if (alleq) {
        int cell = cells[0];
        if (cell < 0) return;
        float4 v0[Nv], v1[Nv];
        #pragma unroll
        for (int n = 0; n < Nv; n++) {
            const float4* p = (const float4*)(x + xoff + n * nstride);
            v0[n] = __ldg(p);
            v1[n] = __ldg(p + 1);
        }
        float4 a0 = v0[0], a1 = v1[0];
        #pragma unroll
        for (int n = 1; n < Nv; n++) {
            a0.x += v0[n].x; a0.y += v0[n].y; a0.z += v0[n].z; a0.w += v0[n].w;
            a1.x += v1[n].x; a1.y += v1[n].y; a1.z += v1[n].z; a1.w += v1[n].w;
        }
        float* p = (float*)g_staging4 + (size_t)cell * Cv + c8;
        red_v4(p, a0);
        red_v4(p + 4, a1);
    } else {
        float4 a0 = make_float4(0, 0, 0, 0), a1 = make_float4(0, 0, 0, 0);
        int cur = -1;
        #pragma unroll
        for (int n = 0; n < Nv; n++) {
            if (cells[n] != cur) {
                if (cur >= 0) {
                    float* p = (float*)g_staging4 + (size_t)cur * Cv + c8;
                    red_v4(p, a0);
                    red_v4(p + 4, a1);
                }
                a0 = make_float4(0, 0, 0, 0);
                a1 = make_float4(0, 0, 0, 0);
                cur = cells[n];
            }
            if (cells[n] >= 0) {
                const float4* p = (const float4*)(x + xoff + n * nstride);
                float4 w0 = __ldg(p), w1 = __ldg(p + 1);
                a0.x += w0.x; a0.y += w0.y; a0.z += w0.z; a0.w += w0.w;
                a1.x += w1.x; a1.y += w1.y; a1.z += w1.z; a1.w += w1.w;
            }
        }
        if (cur >= 0) {
            float* p = (float*)g_staging4 + (size_t)cur * Cv + c8;
            red_v4(p, a0);
            red_v4(p + 4, a1);
        }
    }
}

// ---------------------------------------------------------------------------
// Transpose staging (B, NY, NX, C) -> out (B, C, NY, NX).
// 4 tiles per block, double-buffered smem, software-pipelined: the L2 reads
// for tile i+1 are issued while tile i is transposed through smem. One
// __syncthreads per iteration (LDS_i precedes STS_{i+1} precedes sync_{i+1}
// precedes STS_{i+2} in program order -> no buffer-reuse hazard).
// Staging re-zero at the kernel tail only (R4 lesson: a same-address
// STG-after-LDG parks behind the load in L1tex and stalls the LSU).
// ---------------------------------------------------------------------------
#define TILES_PB 4

__device__ __forceinline__ float4* tile_src(int tl) {
    int gxt = tl % (NXv / 32);
    int t1 = tl / (NXv / 32);
    int gy = t1 % NYv;
    int b = t1 / NYv;
    return g_staging4 + ((size_t)(b * NYv + gy) * NXv + gxt * 32) * (Cv / 4);
}

__global__ __launch_bounds__(256) void fp_transpose_kernel(float* __restrict__ out) {
    __shared__ float tile[2][32 * 65];
    int t = threadIdx.x;
    int tile0 = blockIdx.x * TILES_PB;

    // indices reused every iteration
    int gxA = t >> 4;              // 0..15   (first 256 float4 units)
    int c4A = (t & 15) * 4;
    int gxB = (t + 256) >> 4;      // 16..31  (second 256 units)
    int c4B = c4A;

    // prefetch tile 0
    float4 cur0, cur1, nxt0, nxt1;
    {
        float4* s = tile_src(tile0);
        cur0 = s[t];
        cur1 = s[t + 256];
    }

    #pragma unroll
    for (int i = 0; i < TILES_PB; i++) {
        int tl = tile0 + i;
        float* tb = tile[i & 1];

        tb[gxA * 65 + c4A + 0] = cur0.x;
        tb[gxA * 65 + c4A + 1] = cur0.y;
        tb[gxA * 65 + c4A + 2] = cur0.z;
        tb[gxA * 65 + c4A + 3] = cur0.w;
        tb[gxB * 65 + c4B + 0] = cur1.x;
        tb[gxB * 65 + c4B + 1] = cur1.y;
        tb[gxB * 65 + c4B + 2] = cur1.z;
        tb[gxB * 65 + c4B + 3] = cur1.w;

        // prefetch next tile while this one syncs + drains through smem
        if (i + 1 < TILES_PB) {
            float4* s = tile_src(tl + 1);
            nxt0 = s[t];
            nxt1 = s[t + 256];
        }
        __syncthreads();

        int gxt = tl % (NXv / 32);
        int t1 = tl / (NXv / 32);
        int gy = t1 % NYv;
        int b = t1 / NYv;
        int gx0 = gxt * 32;

        #pragma unroll
        for (int it = 0; it < 2; it++) {
            int uu = t + it * 256;   // 0..511 output float4 units
            int gx4 = uu & 7;        // 4-wide gx group
            int c = uu >> 3;         // 0..63
            float4 o;
            o.x = tb[(gx4 * 4 + 0) * 65 + c];
            o.y = tb[(gx4 * 4 + 1) * 65 + c];
            o.z = tb[(gx4 * 4 + 2) * 65 + c];
            o.w = tb[(gx4 * 4 + 3) * 65 + c];
            float4* dst = (float4*)(out + (size_t)(b * Cv + c) * NYNX +
                                    gy * NXv + gx0 + gx4 * 4);
            *dst = o;
        }
        cur0 = nxt0;
        cur1 = nxt1;
    }

    // Tail: restore staging to zero for the next graph replay (fire-and-
    // forget stores; the matching loads completed long ago).
    const float4 z4 = make_float4(0.f, 0.f, 0.f, 0.f);
    #pragma unroll
    for (int i = 0; i < TILES_PB; i++) {
        float4* s = tile_src(tile0 + i);
        s[t] = z4;
        s[t + 256] = z4;
    }
}

extern "C" void kernel_launch(void* const* d_in, const int* in_sizes, int n_in,
                              void* d_out, int out_size) {
    const float* x = (const float*)d_in[0];
    const float* intr = (const float*)d_in[1];
    const float* pose = (const float*)d_in[2];
    float* out = (float*)d_out;

    // 1) scatter (4 rays per warp, vector atomics into zeroed staging)
    const int P = Bv * Dv * Hv * Wv;      // 161280 rays
    int blocks = P / 4 / 8;               // 5040 blocks of 8 warps
    fp_scatter_kernel<<<blocks, 256>>>(x, intr, pose);

    // 2) transpose staging -> out (pipelined, 4 tiles/block);
    //    re-zeroes staging at its tail
    int tblocks = Bv * NYv * (NXv / 32) / TILES_PB;  // 576
    fp_transpose_kernel<<<tblocks, 256>>>(out);
}